// round 1
// baseline (speedup 1.0000x reference)
#include <cuda_runtime.h>

// TypeAttention reduces algebraically to alpha[e] = 1 / in_degree(dst[e]) per
// relation: all edges into a dst share the same logit, so softmax over the
// segment is uniform. Output = concat over the two relations.

#define MAX_NODES 100000

__device__ int g_cnt_ui[MAX_NODES];
__device__ int g_cnt_iu[MAX_NODES];

__global__ void zero_counts_kernel(int n) {
    int i = blockIdx.x * blockDim.x + threadIdx.x;
    if (i < n) {
        g_cnt_ui[i] = 0;
        g_cnt_iu[i] = 0;
    }
}

__global__ void hist_kernel(const int* __restrict__ dst_ui,
                            const int* __restrict__ dst_iu, int E) {
    int i = blockIdx.x * blockDim.x + threadIdx.x;
    if (i < E) {
        atomicAdd(&g_cnt_ui[dst_ui[i]], 1);
        atomicAdd(&g_cnt_iu[dst_iu[i]], 1);
    }
}

__global__ void gather_kernel(const int* __restrict__ dst_ui,
                              const int* __restrict__ dst_iu,
                              float* __restrict__ out, int E) {
    int i = blockIdx.x * blockDim.x + threadIdx.x;
    if (i < E) {
        out[i]     = 1.0f / (float)g_cnt_ui[dst_ui[i]];
        out[E + i] = 1.0f / (float)g_cnt_iu[dst_iu[i]];
    }
}

extern "C" void kernel_launch(void* const* d_in, const int* in_sizes, int n_in,
                              void* d_out, int out_size) {
    // Input order: h_user, h_item, Wl_user, bl_user, Wl_item, bl_item,
    //              Wr_user, br_user, Wr_item, br_item, attn_w,
    //              src_ui, dst_ui, src_iu, dst_iu
    const int* dst_ui = (const int*)d_in[12];
    const int* dst_iu = (const int*)d_in[14];
    float* out = (float*)d_out;

    int D = in_sizes[3];               // bl_user has D elements
    int Nn = in_sizes[0] / D;          // h_user is (N, D)
    if (Nn > MAX_NODES) Nn = MAX_NODES;
    int E = in_sizes[12];              // dst_ui has E elements

    const int TPB = 256;
    zero_counts_kernel<<<(Nn + TPB - 1) / TPB, TPB>>>(Nn);
    hist_kernel<<<(E + TPB - 1) / TPB, TPB>>>(dst_ui, dst_iu, E);
    gather_kernel<<<(E + TPB - 1) / TPB, TPB>>>(dst_ui, dst_iu, out, E);
}